// round 9
// baseline (speedup 1.0000x reference)
#include <cuda_runtime.h>
#include <stdint.h>

#define BATCH 32
#define NBOX 24564
#define ROW 93
#define NUM_PRED 10
#define DB 64               // boxes per decode CTA
#define NBIN 1024
#define CCAP 3072           // smem candidate capacity (24 B/entry = 72 KB)
#define TARGET 128          // desired compacted candidates per image

typedef unsigned long long u64;

// Scratch (static device globals; zero-initialized at load)
__device__ u64    g_key[BATCH * NBOX];   // dense: 0 = dead, else (score<<32)|(~idx)
__device__ int    g_cls[BATCH * NBOX];
__device__ float4 g_box[BATCH * NBOX];
__device__ int    g_hist[BATCH * NBIN];

// Precise float exp: Cody-Waite + degree-6 FMA poly (~1 ulp), fast-math-proof.
__device__ __forceinline__ float exp_precise(float x) {
    x = fminf(fmaxf(x, -80.0f), 80.0f);
    float kf = rintf(x * 1.4426950408889634f);
    float r  = fmaf(-kf, 0.6931471824645996f, x);
    r        = fmaf(-kf, -1.904654323148236e-09f, r);
    float p  = 1.9875691500e-4f;
    p = fmaf(p, r, 1.3981999507e-3f);
    p = fmaf(p, r, 8.3334519073e-3f);
    p = fmaf(p, r, 4.1665795894e-2f);
    p = fmaf(p, r, 1.6666665459e-1f);
    p = fmaf(p, r, 5.0000000000e-1f);
    p = fmaf(p, r, 1.0f);
    p = fmaf(p, r, 1.0f);
    return p * __int_as_float(((int)kf + 127) << 23);
}

// Thread-per-box decode with smem staging + 1024-bin score-bit histogram.
__global__ __launch_bounds__(DB) void decode_kernel(const float* __restrict__ y) {
    __shared__ float s[DB * ROW];        // 23,808 B
    __shared__ int   h[NBIN];            // 4,096 B
    const int b  = blockIdx.y;
    const int c0 = blockIdx.x * DB;
    const int nb = min(DB, NBOX - c0);
    const int nf4 = (nb * ROW) >> 2;
    const int t = threadIdx.x;

    for (int i = t; i < NBIN; i += DB) h[i] = 0;
    const float4* src = (const float4*)(y + ((size_t)b * NBOX + c0) * ROW);
    float4* dst = (float4*)s;
    for (int i = t; i < nf4; i += DB) dst[i] = src[i];
    __syncthreads();

    if (t < nb) {
        const float* row = s + t * ROW;
        // argmax over 81 classes; '>' keeps first occurrence (jnp.argmax)
        float best = row[0]; int bi = 0;
        #pragma unroll
        for (int c = 1; c < 81; c++) {
            float v = row[c];
            if (v > best) { best = v; bi = c; }
        }
        const int box = c0 + t;
        const int p = b * NBOX + box;
        if (bi != 0 && best >= 0.5f) {
            float o0 = row[81], o1 = row[82], o2 = row[83], o3 = row[84];
            float cxp = row[85], cyp = row[86], wp = row[87], hp = row[88];
            float va = row[89], vb = row[90], vc = row[91], vd = row[92];
            float cx = o0 * va * wp + cxp;
            float cy = o1 * vb * hp + cyp;
            float w  = exp_precise(o2 * vc) * wp;
            float hh = exp_precise(o3 * vd) * hp;
            float4 bx;
            bx.x = (cx - 0.5f * w)  * 512.0f;
            bx.y = (cy - 0.5f * hh) * 512.0f;
            bx.z = (cx + 0.5f * w)  * 512.0f;
            bx.w = (cy + 0.5f * hh) * 512.0f;
            unsigned sb = __float_as_uint(best);
            g_key[p] = ((u64)sb << 32) | (u64)(0xFFFFFFFFu - (unsigned)box);
            g_cls[p] = bi;
            g_box[p] = bx;
            int bin = min(NBIN - 1, (int)((sb - 0x3F000000u) >> 13));
            atomicAdd(&h[bin], 1);
        } else {
            g_key[p] = 0ull;
        }
    }
    __syncthreads();
    for (int i = t; i < NBIN; i += DB) {
        int c = h[i];
        if (c) atomicAdd(&g_hist[b * NBIN + i], c);
    }
}

__device__ __forceinline__ bool iou_gt(const float4& a, const float4& q) {
    float iw = fminf(a.z, q.z) - fmaxf(a.x, q.x); iw = fmaxf(iw, 0.0f);
    float ih = fminf(a.w, q.w) - fmaxf(a.y, q.y); ih = fmaxf(ih, 0.0f);
    float inter  = iw * ih;
    float area_a = (a.z - a.x) * (a.w - a.y);
    float area_q = (q.z - q.x) * (q.w - q.y);
    return inter / (area_a + area_q - inter + 1e-12f) > 0.35f;
}

// Fused post-processing: one 256-thread CTA per image.
// Floor from 1024-bin hist (raised one bin if cut-bin would overflow CCAP ->
// smem set NEVER overflows). Compact keys >= floor into smem. Warp 0 runs
// greedy NMS; exact below-floor continuation only if <10 picks remain (rare).
__global__ __launch_bounds__(256) void post_kernel(float* __restrict__ out) {
    extern __shared__ __align__(16) char dsm[];
    float4* s_box = (float4*)dsm;                    // CCAP
    u64*    s_key = (u64*)(s_box + CCAP);            // CCAP
    __shared__ int s_h[NBIN];
    __shared__ int s_c[256];
    __shared__ int s_cnt;
    __shared__ u64 s_floor;

    const int b    = blockIdx.x;
    const int tid  = threadIdx.x;
    const int lane = tid & 31;
    const int base = b * NBOX;
    const unsigned FULL = 0xffffffffu;

    if (tid < NUM_PRED * 6) out[b * NUM_PRED * 6 + tid] = 0.0f;
    if (tid == 0) s_cnt = 0;
    #pragma unroll
    for (int j = 0; j < NBIN / 256; j++) {           // read + zero hist
        int i = tid + j * 256;
        s_h[i] = g_hist[b * NBIN + i];
        g_hist[b * NBIN + i] = 0;
    }
    __syncthreads();
    // chunk sums: s_c[t] = sum of bins [4t, 4t+4)
    {
        int acc = s_h[tid*4] + s_h[tid*4+1] + s_h[tid*4+2] + s_h[tid*4+3];
        s_c[tid] = acc;
    }
    __syncthreads();

    if (tid < 32) {
        // lane sums bins [32*lane, 32*lane+32) via 8 chunk sums
        int sum = 0;
        #pragma unroll
        for (int j = 0; j < 8; j++) sum += s_c[lane * 8 + j];
        // suffix scan (cum from bin 32*lane upward)
        int suf = sum;
        #pragma unroll
        for (int o = 1; o < 32; o <<= 1) {
            int v = __shfl_down_sync(FULL, suf, o);
            if (lane + o < 32) suf += v;
        }
        unsigned mask = __ballot_sync(FULL, suf >= TARGET);
        int L = (mask == 0u) ? -1 : (31 - __clz(mask));
        int cumab = __shfl_down_sync(FULL, suf, 1);          // suf[lane+1]
        cumab = __shfl_sync(FULL, (L >= 0 && L < 31) ? 0 : 0, 0) // placeholder no-op
              , cumab = __shfl_sync(FULL, cumab, (L < 0) ? 0 : L); // cum above L's block
        if (lane == 0) {
            int T;
            if (L < 0) {
                T = 0;                                        // few cands: admit all
            } else {
                int cum = (L == 31) ? 0 : cumab;
                T = L * 32;
                for (int jb = 31; jb >= 0; jb--) {
                    int bin = L * 32 + jb;
                    cum += s_h[bin];
                    if (cum >= TARGET) { T = bin; break; }
                }
                if (cum > CCAP) T = T + 1;   // cum(T+1) < TARGET <= CCAP guaranteed
            }
            unsigned bits = 0x3F000000u + ((unsigned)T << 13);
            s_floor = (u64)bits << 32;
        }
    }
    __syncthreads();
    const u64 floork = s_floor;

    // ---- compact: batched loads + early-skip aggregation ----
    for (int g = 0; g < 12; g++) {
        u64 k[8];
        #pragma unroll
        for (int j = 0; j < 8; j++) {
            int idx = tid + (g * 8 + j) * 256;
            k[j] = (idx < NBOX) ? g_key[base + idx] : 0ull;
        }
        #pragma unroll
        for (int j = 0; j < 8; j++) {
            bool pass = (k[j] >= floork);
            unsigned m = __ballot_sync(FULL, pass);
            if (m == 0u) continue;                   // common case
            if (pass) {
                int leader = __ffs(m) - 1;
                int wb;
                if (lane == leader) wb = atomicAdd(&s_cnt, __popc(m));
                wb = __shfl_sync(m, wb, leader);
                int slot = wb + __popc(m & ((1u << lane) - 1u));
                if (slot < CCAP) {
                    int idx = tid + (g * 8 + j) * 256;
                    s_key[slot] = k[j];
                    s_box[slot] = g_box[base + idx];
                }
            }
        }
    }
    __syncthreads();

    // ---- warp 0: greedy NMS over the score-prefix set ----
    if (tid >= 32) return;
    const int M = min(s_cnt, CCAP);
    float4 pick = make_float4(0.f, 0.f, 0.f, 0.f);   // lane i holds pick i
    int np = 0;

    while (np < NUM_PRED) {
        u64 lb = 0; int ls = -1;
        for (int i = lane; i < M; i += 32) {
            u64 k = s_key[i];
            if (k > lb) { lb = k; ls = i; }
        }
        u64 gb = lb;
        #pragma unroll
        for (int o = 16; o > 0; o >>= 1) {
            u64 t2 = __shfl_xor_sync(FULL, gb, o);
            gb = t2 > gb ? t2 : gb;
        }
        if (gb == 0ull) break;                       // prefix set exhausted
        unsigned own = __ballot_sync(FULL, lb == gb);
        int slot = __shfl_sync(FULL, ls, __ffs(own) - 1);
        float4 cand = s_box[slot];
        if (lane == (__ffs(own) - 1)) s_key[slot] = 0ull;
        __syncwarp();
        bool hit = (lane < np) && iou_gt(cand, pick);
        if (__ballot_sync(FULL, hit) == 0u) {
            if (lane == np) pick = cand;
            if (lane == 0) {
                unsigned orig = 0xFFFFFFFFu - (unsigned)gb;
                float* o = out + (b * NUM_PRED + np) * 6;
                o[0] = (float)g_cls[base + orig];
                o[1] = __uint_as_float((unsigned)(gb >> 32));
                o[2] = cand.x; o[3] = cand.y; o[4] = cand.z; o[5] = cand.w;
            }
            np++;
        }
    }

    // exact continuation below the floor (rare: <10 picks survived)
    u64 cont = floork;
    while (np < NUM_PRED) {
        u64 lb = 0;
        for (int i = lane; i < NBOX; i += 32) {
            u64 k = g_key[base + i];
            if (k < cont && k > lb) lb = k;
        }
        u64 gb = lb;
        #pragma unroll
        for (int o = 16; o > 0; o >>= 1) {
            u64 t2 = __shfl_xor_sync(FULL, gb, o);
            gb = t2 > gb ? t2 : gb;
        }
        if (gb == 0ull) break;
        cont = gb;
        unsigned orig = 0xFFFFFFFFu - (unsigned)gb;
        float4 cand = g_box[base + orig];
        bool hit = (lane < np) && iou_gt(cand, pick);
        if (__ballot_sync(FULL, hit) == 0u) {
            if (lane == np) pick = cand;
            if (lane == 0) {
                float* o = out + (b * NUM_PRED + np) * 6;
                o[0] = (float)g_cls[base + orig];
                o[1] = __uint_as_float((unsigned)(gb >> 32));
                o[2] = cand.x; o[3] = cand.y; o[4] = cand.z; o[5] = cand.w;
            }
            np++;
        }
    }
}

extern "C" void kernel_launch(void* const* d_in, const int* in_sizes, int n_in,
                              void* d_out, int out_size) {
    const float* y = (const float*)d_in[0];
    float* out = (float*)d_out;

    cudaFuncSetAttribute(post_kernel, cudaFuncAttributeMaxDynamicSharedMemorySize,
                         CCAP * 24);

    dim3 dgrid((NBOX + DB - 1) / DB, BATCH);
    decode_kernel<<<dgrid, DB>>>(y);

    post_kernel<<<BATCH, 256, CCAP * 24>>>(out);
}

// round 10
// speedup vs baseline: 1.0190x; 1.0190x over previous
#include <cuda_runtime.h>
#include <stdint.h>

#define BATCH 32
#define NBOX 24564
#define ROW 93
#define NUM_PRED 10
#define DB 64               // boxes per decode CTA
#define K_SEL 192           // exact top-K selected per image

typedef unsigned long long u64;

// Scratch (static device globals; zero-initialized at load)
__device__ u64    g_key[BATCH * NBOX];   // dense: 0 = dead, else (score<<32)|(~idx)
__device__ int    g_cls[BATCH * NBOX];
__device__ float4 g_box[BATCH * NBOX];
__device__ u64    g_buf[2][BATCH * NBOX];  // radix-select ping-pong

// Precise float exp: Cody-Waite + degree-6 FMA poly (~1 ulp), fast-math-proof.
__device__ __forceinline__ float exp_precise(float x) {
    x = fminf(fmaxf(x, -80.0f), 80.0f);
    float kf = rintf(x * 1.4426950408889634f);
    float r  = fmaf(-kf, 0.6931471824645996f, x);
    r        = fmaf(-kf, -1.904654323148236e-09f, r);
    float p  = 1.9875691500e-4f;
    p = fmaf(p, r, 1.3981999507e-3f);
    p = fmaf(p, r, 8.3334519073e-3f);
    p = fmaf(p, r, 4.1665795894e-2f);
    p = fmaf(p, r, 1.6666665459e-1f);
    p = fmaf(p, r, 5.0000000000e-1f);
    p = fmaf(p, r, 1.0f);
    p = fmaf(p, r, 1.0f);
    return p * __int_as_float(((int)kf + 127) << 23);
}

__device__ __forceinline__ void cp16(uint32_t dst_smem, const void* src) {
    asm volatile("cp.async.cg.shared.global [%0], [%1], 16;"
                 :: "r"(dst_smem), "l"(src));
}

// Thread-per-box decode: cp.async staging into smem, per-thread argmax.
__global__ __launch_bounds__(DB) void decode_kernel(const float* __restrict__ y) {
    __shared__ float s[DB * ROW];
    const int b  = blockIdx.y;
    const int c0 = blockIdx.x * DB;
    const int nb = min(DB, NBOX - c0);
    const int nf4 = (nb * ROW) >> 2;
    const int t = threadIdx.x;

    {
        const float4* src = (const float4*)(y + ((size_t)b * NBOX + c0) * ROW);
        uint32_t sbase;
        asm("{ .reg .u64 tmp; cvta.to.shared.u64 tmp, %1; cvt.u32.u64 %0, tmp; }"
            : "=r"(sbase) : "l"(s));
        for (int i = t; i < nf4; i += DB) cp16(sbase + i * 16, src + i);
        asm volatile("cp.async.commit_group;" ::: "memory");
        asm volatile("cp.async.wait_group 0;" ::: "memory");
    }
    __syncthreads();

    if (t >= nb) return;
    const float* row = s + t * ROW;
    // argmax over 81 classes; '>' keeps first occurrence (jnp.argmax)
    float best = row[0]; int bi = 0;
    #pragma unroll
    for (int c = 1; c < 81; c++) {
        float v = row[c];
        if (v > best) { best = v; bi = c; }
    }
    const int box = c0 + t;
    const int p = b * NBOX + box;
    if (bi != 0 && best >= 0.5f) {
        float o0 = row[81], o1 = row[82], o2 = row[83], o3 = row[84];
        float cxp = row[85], cyp = row[86], wp = row[87], hp = row[88];
        float va = row[89], vb = row[90], vc = row[91], vd = row[92];
        float cx = o0 * va * wp + cxp;
        float cy = o1 * vb * hp + cyp;
        float w  = exp_precise(o2 * vc) * wp;
        float hh = exp_precise(o3 * vd) * hp;
        float4 bx;
        bx.x = (cx - 0.5f * w)  * 512.0f;
        bx.y = (cy - 0.5f * hh) * 512.0f;
        bx.z = (cx + 0.5f * w)  * 512.0f;
        bx.w = (cy + 0.5f * hh) * 512.0f;
        g_key[p] = ((u64)__float_as_uint(best) << 32) |
                   (u64)(0xFFFFFFFFu - (unsigned)box);
        g_cls[p] = bi;
        g_box[p] = bx;
    } else {
        g_key[p] = 0ull;
    }
}

__device__ __forceinline__ bool iou_gt(const float4& a, const float4& q) {
    float iw = fminf(a.z, q.z) - fmaxf(a.x, q.x); iw = fmaxf(iw, 0.0f);
    float ih = fminf(a.w, q.w) - fmaxf(a.y, q.y); ih = fmaxf(ih, 0.0f);
    float inter  = iw * ih;
    float area_a = (a.z - a.x) * (a.w - a.y);
    float area_q = (q.z - q.x) * (q.w - q.y);
    return inter / (area_a + area_q - inter + 1e-12f) > 0.35f;
}

// One 256-thread CTA per image.
// Stage 1: exact top-K_SEL keys via MSB-first 8-bit radix select (ties resolved
//          by full 64-bit key, which embeds ~idx -> reference order).
// Stage 2: warp 0 greedy NMS over the selected set (smem); exact continuation
//          below the selection minimum if <10 picks survive (rare).
__global__ __launch_bounds__(256) void post_kernel(float* __restrict__ out) {
    __shared__ int    s_hist[256];
    __shared__ u64    s_key[K_SEL];
    __shared__ float4 s_box[K_SEL];
    __shared__ int    s_selcnt, s_bufcnt, s_r, s_D, s_A, s_bc;
    __shared__ u64    s_kmin;

    const int b    = blockIdx.x;
    const int tid  = threadIdx.x;
    const int lane = tid & 31;
    const int base = b * NBOX;
    const unsigned FULL = 0xffffffffu;

    if (tid < NUM_PRED * 6) out[b * NUM_PRED * 6 + tid] = 0.0f;
    if (tid == 0) { s_selcnt = 0; s_r = K_SEL; s_kmin = ~0ull; }

    int curcnt = NBOX;
    for (int p = 0; p < 8; p++) {
        const int sh = 56 - 8 * p;
        s_hist[tid] = 0;
        if (tid == 0) s_bufcnt = 0;
        __syncthreads();

        const u64* src = (p == 0) ? (g_key + base)
                                  : (g_buf[(p - 1) & 1] + base);
        // ---- hist scan (batched for MLP) ----
        {
            int nr = (curcnt + 2047) & ~2047;
            for (int i0 = tid; i0 < nr; i0 += 2048) {
                u64 kk[8];
                #pragma unroll
                for (int j = 0; j < 8; j++) {
                    int i = i0 + j * 256;
                    kk[j] = (i < curcnt) ? src[i] : 0ull;
                }
                #pragma unroll
                for (int j = 0; j < 8; j++)
                    if (kk[j]) atomicAdd(&s_hist[(int)((kk[j] >> sh) & 255)], 1);
            }
        }
        __syncthreads();

        // ---- find cut bin (warp 0) ----
        if (tid < 32) {
            int c[8], lsum = 0;
            #pragma unroll
            for (int j = 0; j < 8; j++) { c[j] = s_hist[lane * 8 + j]; lsum += c[j]; }
            int suf = lsum;                       // suffix over lanes >= lane
            #pragma unroll
            for (int o = 1; o < 32; o <<= 1) {
                int v = __shfl_down_sync(FULL, suf, o);
                if (lane + o < 32) suf += v;
            }
            int r = s_r;
            unsigned mask = __ballot_sync(FULL, suf >= r);
            int sufnext = __shfl_down_sync(FULL, suf, 1);
            if (lane == 31) sufnext = 0;
            if (mask == 0u) {
                if (lane == 0) { s_D = -1; s_A = 0; s_bc = 0; }
            } else {
                int L = 31 - __clz(mask);         // highest lane with suf >= r
                if (lane == L) {
                    int cum = sufnext;            // count(digit >= (L+1)*8)
                    int D = L * 8, A = cum, bc = 0;
                    #pragma unroll
                    for (int jb = 7; jb >= 0; jb--) {
                        if (cum + c[jb] >= r) { D = L * 8 + jb; A = cum; bc = c[jb]; break; }
                        cum += c[jb];
                    }
                    s_D = D; s_A = A; s_bc = bc;
                }
            }
        }
        __syncthreads();
        const int D = s_D, A = s_A, bc = s_bc, r = s_r;
        const bool takeAll = (D < 0) || (bc == r - A);

        // ---- route scan ----
        u64* dstbuf = g_buf[p & 1] + base;
        int nr = (curcnt + 255) & ~255;
        for (int i = tid; i < nr; i += 256) {
            u64 k = (i < curcnt) ? src[i] : 0ull;
            int d = (int)((k >> sh) & 255);
            bool sel = (k != 0ull) && (D < 0 || d > D || (d == D && takeAll));
            bool tob = (k != 0ull) && !sel && (d == D);
            unsigned ms = __ballot_sync(FULL, sel);
            if (sel) {
                int leader = __ffs(ms) - 1; int wb;
                if (lane == leader) wb = atomicAdd(&s_selcnt, __popc(ms));
                wb = __shfl_sync(ms, wb, leader);
                s_key[wb + __popc(ms & ((1u << lane) - 1u))] = k;
            }
            unsigned mb = __ballot_sync(FULL, tob);
            if (tob) {
                int leader = __ffs(mb) - 1; int wb;
                if (lane == leader) wb = atomicAdd(&s_bufcnt, __popc(mb));
                wb = __shfl_sync(mb, wb, leader);
                dstbuf[wb + __popc(mb & ((1u << lane) - 1u))] = k;
            }
        }
        __syncthreads();
        if (takeAll) break;
        if (tid == 0) s_r = r - A;
        curcnt = s_bufcnt;
        __syncthreads();
    }

    // ---- fetch boxes + selection min ----
    const int M = s_selcnt;                       // <= K_SEL by construction
    for (int i = tid; i < M; i += 256) {
        u64 k = s_key[i];
        atomicMin(&s_kmin, k);
        unsigned orig = 0xFFFFFFFFu - (unsigned)k;
        s_box[i] = g_box[base + orig];
    }
    __syncthreads();

    // ---- warp 0: greedy NMS ----
    if (tid >= 32) return;
    float4 pick = make_float4(0.f, 0.f, 0.f, 0.f);  // lane i holds pick i
    int np = 0;

    while (np < NUM_PRED) {
        u64 lb = 0; int ls = -1;
        #pragma unroll
        for (int j = 0; j < (K_SEL + 31) / 32; j++) {
            int i = lane + j * 32;
            if (i < M) {
                u64 k = s_key[i];
                if (k > lb) { lb = k; ls = i; }
            }
        }
        u64 gb = lb;
        #pragma unroll
        for (int o = 16; o > 0; o >>= 1) {
            u64 t2 = __shfl_xor_sync(FULL, gb, o);
            gb = t2 > gb ? t2 : gb;
        }
        if (gb == 0ull) break;                    // selected set exhausted
        unsigned own = __ballot_sync(FULL, lb == gb);
        int slot = __shfl_sync(FULL, ls, __ffs(own) - 1);
        float4 cand = s_box[slot];
        if (lane == (__ffs(own) - 1)) s_key[slot] = 0ull;
        __syncwarp();
        bool hit = (lane < np) && iou_gt(cand, pick);
        if (__ballot_sync(FULL, hit) == 0u) {
            if (lane == np) pick = cand;
            if (lane == 0) {
                unsigned orig = 0xFFFFFFFFu - (unsigned)gb;
                float* o = out + (b * NUM_PRED + np) * 6;
                o[0] = (float)g_cls[base + orig];
                o[1] = __uint_as_float((unsigned)(gb >> 32));
                o[2] = cand.x; o[3] = cand.y; o[4] = cand.z; o[5] = cand.w;
            }
            np++;
        }
    }

    // exact continuation below the selection (rare: >K_SEL-10 suppressions)
    u64 cont = s_kmin;
    while (np < NUM_PRED) {
        u64 lb = 0;
        for (int i = lane; i < NBOX; i += 32) {
            u64 k = g_key[base + i];
            if (k < cont && k > lb) lb = k;
        }
        u64 gb = lb;
        #pragma unroll
        for (int o = 16; o > 0; o >>= 1) {
            u64 t2 = __shfl_xor_sync(FULL, gb, o);
            gb = t2 > gb ? t2 : gb;
        }
        if (gb == 0ull) break;
        cont = gb;
        unsigned orig = 0xFFFFFFFFu - (unsigned)gb;
        float4 cand = g_box[base + orig];
        bool hit = (lane < np) && iou_gt(cand, pick);
        if (__ballot_sync(FULL, hit) == 0u) {
            if (lane == np) pick = cand;
            if (lane == 0) {
                float* o = out + (b * NUM_PRED + np) * 6;
                o[0] = (float)g_cls[base + orig];
                o[1] = __uint_as_float((unsigned)(gb >> 32));
                o[2] = cand.x; o[3] = cand.y; o[4] = cand.z; o[5] = cand.w;
            }
            np++;
        }
    }
}

extern "C" void kernel_launch(void* const* d_in, const int* in_sizes, int n_in,
                              void* d_out, int out_size) {
    const float* y = (const float*)d_in[0];
    float* out = (float*)d_out;

    dim3 dgrid((NBOX + DB - 1) / DB, BATCH);
    decode_kernel<<<dgrid, DB>>>(y);

    post_kernel<<<BATCH, 256>>>(out);
}

// round 11
// speedup vs baseline: 1.4977x; 1.4699x over previous
#include <cuda_runtime.h>
#include <stdint.h>

#define BATCH 32
#define NBOX 24564
#define ROW 93
#define NUM_PRED 10
#define DB 64               // boxes per decode CTA
#define NBIN 1024
#define CCAP 3072           // smem candidate capacity (24 B/entry = 72 KB)
#define TARGET 128

typedef unsigned long long u64;

// Scratch (static device globals; zero-initialized at load)
__device__ u64    g_key[BATCH * NBOX];   // dense: 0 = dead, else (score<<32)|(~idx)
__device__ int    g_cls[BATCH * NBOX];
__device__ float4 g_box[BATCH * NBOX];
__device__ int    g_hist[BATCH * NBIN];

// Precise float exp: Cody-Waite + degree-6 FMA poly (~1 ulp), fast-math-proof.
__device__ __forceinline__ float exp_precise(float x) {
    x = fminf(fmaxf(x, -80.0f), 80.0f);
    float kf = rintf(x * 1.4426950408889634f);
    float r  = fmaf(-kf, 0.6931471824645996f, x);
    r        = fmaf(-kf, -1.904654323148236e-09f, r);
    float p  = 1.9875691500e-4f;
    p = fmaf(p, r, 1.3981999507e-3f);
    p = fmaf(p, r, 8.3334519073e-3f);
    p = fmaf(p, r, 4.1665795894e-2f);
    p = fmaf(p, r, 1.6666665459e-1f);
    p = fmaf(p, r, 5.0000000000e-1f);
    p = fmaf(p, r, 1.0f);
    p = fmaf(p, r, 1.0f);
    return p * __int_as_float(((int)kf + 127) << 23);
}

__device__ __forceinline__ void cp16(uint32_t dst_smem, const void* src) {
    asm volatile("cp.async.cg.shared.global [%0], [%1], 16;"
                 :: "r"(dst_smem), "l"(src));
}

// Thread-per-box decode: cp.async staging, per-thread argmax, 1024-bin
// score-bit histogram (bin = (bits - 0x3F000000) >> 13, clamped).
__global__ __launch_bounds__(DB) void decode_kernel(const float* __restrict__ y) {
    __shared__ float s[DB * ROW];
    __shared__ int   h[NBIN];
    const int b  = blockIdx.y;
    const int c0 = blockIdx.x * DB;
    const int nb = min(DB, NBOX - c0);
    const int nf4 = (nb * ROW) >> 2;
    const int t = threadIdx.x;

    #pragma unroll
    for (int j = 0; j < NBIN / DB; j++) h[t + j * DB] = 0;
    {
        const float4* src = (const float4*)(y + ((size_t)b * NBOX + c0) * ROW);
        uint32_t sbase;
        asm("{ .reg .u64 tmp; cvta.to.shared.u64 tmp, %1; cvt.u32.u64 %0, tmp; }"
            : "=r"(sbase) : "l"(s));
        for (int i = t; i < nf4; i += DB) cp16(sbase + i * 16, src + i);
        asm volatile("cp.async.commit_group;" ::: "memory");
        asm volatile("cp.async.wait_group 0;" ::: "memory");
    }
    __syncthreads();

    if (t < nb) {
        const float* row = s + t * ROW;
        // argmax over 81 classes; '>' keeps first occurrence (jnp.argmax)
        float best = row[0]; int bi = 0;
        #pragma unroll
        for (int c = 1; c < 81; c++) {
            float v = row[c];
            if (v > best) { best = v; bi = c; }
        }
        const int box = c0 + t;
        const int p = b * NBOX + box;
        if (bi != 0 && best >= 0.5f) {
            float o0 = row[81], o1 = row[82], o2 = row[83], o3 = row[84];
            float cxp = row[85], cyp = row[86], wp = row[87], hp = row[88];
            float va = row[89], vb = row[90], vc = row[91], vd = row[92];
            float cx = o0 * va * wp + cxp;
            float cy = o1 * vb * hp + cyp;
            float w  = exp_precise(o2 * vc) * wp;
            float hh = exp_precise(o3 * vd) * hp;
            float4 bx;
            bx.x = (cx - 0.5f * w)  * 512.0f;
            bx.y = (cy - 0.5f * hh) * 512.0f;
            bx.z = (cx + 0.5f * w)  * 512.0f;
            bx.w = (cy + 0.5f * hh) * 512.0f;
            unsigned sb = __float_as_uint(best);
            g_key[p] = ((u64)sb << 32) | (u64)(0xFFFFFFFFu - (unsigned)box);
            g_cls[p] = bi;
            g_box[p] = bx;
            int bin = min(NBIN - 1, (int)((sb - 0x3F000000u) >> 13));
            atomicAdd(&h[bin], 1);
        } else {
            g_key[p] = 0ull;
        }
    }
    __syncthreads();
    #pragma unroll
    for (int j = 0; j < NBIN / DB; j++) {
        int i = t + j * DB;
        int c = h[i];
        if (c) atomicAdd(&g_hist[b * NBIN + i], c);   // <= nb nonzero bins/CTA
    }
}

__device__ __forceinline__ bool iou_gt(const float4& a, const float4& q) {
    float iw = fminf(a.z, q.z) - fmaxf(a.x, q.x); iw = fmaxf(iw, 0.0f);
    float ih = fminf(a.w, q.w) - fmaxf(a.y, q.y); ih = fmaxf(ih, 0.0f);
    float inter  = iw * ih;
    float area_a = (a.z - a.x) * (a.w - a.y);
    float area_q = (q.z - q.x) * (q.w - q.y);
    return inter / (area_a + area_q - inter + 1e-12f) > 0.35f;
}

// One 256-thread CTA per image. Floor from 1024-bin hist (score-prefix set,
// >= TARGET cands unless fewer exist). Compact keys >= floor into smem.
// Warp 0 greedy NMS; exact below-floor continuation if <10 picks (rare).
__global__ __launch_bounds__(256) void post_kernel(float* __restrict__ out) {
    extern __shared__ __align__(16) char dsm[];
    float4* s_box = (float4*)dsm;                    // CCAP
    u64*    s_key = (u64*)(s_box + CCAP);            // CCAP
    __shared__ int s_h[NBIN];
    __shared__ int s_c[256];
    __shared__ int s_cnt;
    __shared__ u64 s_floor;

    const int b    = blockIdx.x;
    const int tid  = threadIdx.x;
    const int lane = tid & 31;
    const int base = b * NBOX;
    const unsigned FULL = 0xffffffffu;

    if (tid < NUM_PRED * 6) out[b * NUM_PRED * 6 + tid] = 0.0f;
    if (tid == 0) s_cnt = 0;
    #pragma unroll
    for (int j = 0; j < NBIN / 256; j++) {           // read + zero hist
        int i = tid + j * 256;
        s_h[i] = g_hist[b * NBIN + i];
        g_hist[b * NBIN + i] = 0;
    }
    __syncthreads();
    s_c[tid] = s_h[tid*4] + s_h[tid*4+1] + s_h[tid*4+2] + s_h[tid*4+3];
    __syncthreads();

    // ---- floor finder (warp 0) ----
    if (tid < 32) {
        // W = count of bins in block [32*lane, 32*lane+32)
        int W = 0;
        #pragma unroll
        for (int j = 0; j < 8; j++) W += s_c[lane * 8 + j];
        // inclusive suffix sum over lanes: suf[lane] = sum_{l>=lane} W[l]
        int suf = W;
        #pragma unroll
        for (int o = 1; o < 32; o <<= 1) {
            int v = __shfl_down_sync(FULL, suf, o);
            if (lane + o < 32) suf += v;
        }
        int sufnext = __shfl_down_sync(FULL, suf, 1);   // suf[lane+1]
        if (lane == 31) sufnext = 0;
        unsigned mask = __ballot_sync(FULL, suf >= TARGET);
        if (mask == 0u) {
            if (lane == 0)                              // few cands: admit all
                s_floor = ((u64)0x3F000000u) << 32;
        } else {
            int L = 31 - __clz(mask);   // last lane with suf >= TARGET (suf non-increasing)
            if (lane == L) {
                int cum = sufnext;      // count of bins >= 32*(L+1); < TARGET
                int T = 32 * L;
                #pragma unroll
                for (int jb = 31; jb >= 0; jb--) {
                    cum += s_h[32 * L + jb];
                    if (cum >= TARGET) { T = 32 * L + jb; break; }  // must hit
                }
                s_floor = ((u64)(0x3F000000u + ((unsigned)T << 13))) << 32;
            }
        }
    }
    __syncthreads();
    const u64 floork = s_floor;

    // ---- compact: batched loads + early-skip aggregation ----
    for (int g = 0; g < 12; g++) {
        u64 k[8];
        #pragma unroll
        for (int j = 0; j < 8; j++) {
            int idx = tid + (g * 8 + j) * 256;
            k[j] = (idx < NBOX) ? g_key[base + idx] : 0ull;
        }
        #pragma unroll
        for (int j = 0; j < 8; j++) {
            bool pass = (k[j] >= floork);                // floork>0 => implies alive
            unsigned m = __ballot_sync(FULL, pass);
            if (m == 0u) continue;                       // common case
            if (pass) {
                int leader = __ffs(m) - 1;
                int wb;
                if (lane == leader) wb = atomicAdd(&s_cnt, __popc(m));
                wb = __shfl_sync(m, wb, leader);
                int slot = wb + __popc(m & ((1u << lane) - 1u));
                if (slot < CCAP) {
                    int idx = tid + (g * 8 + j) * 256;
                    s_key[slot] = k[j];
                    s_box[slot] = g_box[base + idx];
                }
            }
        }
    }
    __syncthreads();

    // ---- warp 0: greedy NMS over the score-prefix set ----
    if (tid >= 32) return;
    const bool fast = (s_cnt <= CCAP);                   // paranoia guard
    const int M = fast ? s_cnt : 0;
    float4 pick = make_float4(0.f, 0.f, 0.f, 0.f);       // lane i holds pick i
    int np = 0;

    while (np < NUM_PRED) {
        u64 lb = 0; int ls = -1;
        for (int i = lane; i < M; i += 32) {
            u64 k = s_key[i];
            if (k > lb) { lb = k; ls = i; }
        }
        u64 gb = lb;
        #pragma unroll
        for (int o = 16; o > 0; o >>= 1) {
            u64 t2 = __shfl_xor_sync(FULL, gb, o);
            gb = t2 > gb ? t2 : gb;
        }
        if (gb == 0ull) break;                           // prefix set exhausted
        unsigned own = __ballot_sync(FULL, lb == gb);
        int slot = __shfl_sync(FULL, ls, __ffs(own) - 1);
        float4 cand = s_box[slot];
        if (lane == (__ffs(own) - 1)) s_key[slot] = 0ull;
        __syncwarp();
        bool hit = (lane < np) && iou_gt(cand, pick);
        if (__ballot_sync(FULL, hit) == 0u) {
            if (lane == np) pick = cand;
            if (lane == 0) {
                unsigned orig = 0xFFFFFFFFu - (unsigned)gb;
                float* o = out + (b * NUM_PRED + np) * 6;
                o[0] = (float)g_cls[base + orig];
                o[1] = __uint_as_float((unsigned)(gb >> 32));
                o[2] = cand.x; o[3] = cand.y; o[4] = cand.z; o[5] = cand.w;
            }
            np++;
        }
    }

    // exact continuation below the floor (rare: <10 picks survived / overflow)
    u64 cont = fast ? floork : ~0ull;
    while (np < NUM_PRED) {
        u64 lb = 0;
        for (int i = lane; i < NBOX; i += 32) {
            u64 k = g_key[base + i];
            if (k < cont && k > lb) lb = k;
        }
        u64 gb = lb;
        #pragma unroll
        for (int o = 16; o > 0; o >>= 1) {
            u64 t2 = __shfl_xor_sync(FULL, gb, o);
            gb = t2 > gb ? t2 : gb;
        }
        if (gb == 0ull) break;
        cont = gb;
        unsigned orig = 0xFFFFFFFFu - (unsigned)gb;
        float4 cand = g_box[base + orig];
        bool hit = (lane < np) && iou_gt(cand, pick);
        if (__ballot_sync(FULL, hit) == 0u) {
            if (lane == np) pick = cand;
            if (lane == 0) {
                float* o = out + (b * NUM_PRED + np) * 6;
                o[0] = (float)g_cls[base + orig];
                o[1] = __uint_as_float((unsigned)(gb >> 32));
                o[2] = cand.x; o[3] = cand.y; o[4] = cand.z; o[5] = cand.w;
            }
            np++;
        }
    }
}

extern "C" void kernel_launch(void* const* d_in, const int* in_sizes, int n_in,
                              void* d_out, int out_size) {
    const float* y = (const float*)d_in[0];
    float* out = (float*)d_out;

    cudaFuncSetAttribute(post_kernel, cudaFuncAttributeMaxDynamicSharedMemorySize,
                         CCAP * 24);

    dim3 dgrid((NBOX + DB - 1) / DB, BATCH);
    decode_kernel<<<dgrid, DB>>>(y);

    post_kernel<<<BATCH, 256, CCAP * 24>>>(out);
}

// round 12
// speedup vs baseline: 1.7674x; 1.1800x over previous
#include <cuda_runtime.h>
#include <stdint.h>

#define BATCH 32
#define NBOX 24564
#define ROW 93
#define NUM_PRED 10
#define DB 64               // boxes per decode CTA
#define NBIN 1024
#define CCAP 3072           // smem candidate capacity (24 B/entry = 72 KB)
#define TARGET 128
#define PT 1024             // post_kernel threads

typedef unsigned long long u64;

// Scratch (static device globals; zero-initialized at load)
__device__ u64    g_key[BATCH * NBOX];   // dense: 0 = dead, else (score<<32)|(~idx)
__device__ int    g_cls[BATCH * NBOX];
__device__ float4 g_box[BATCH * NBOX];
__device__ int    g_hist[BATCH * NBIN];

// Precise float exp: Cody-Waite + degree-6 FMA poly (~1 ulp), fast-math-proof.
__device__ __forceinline__ float exp_precise(float x) {
    x = fminf(fmaxf(x, -80.0f), 80.0f);
    float kf = rintf(x * 1.4426950408889634f);
    float r  = fmaf(-kf, 0.6931471824645996f, x);
    r        = fmaf(-kf, -1.904654323148236e-09f, r);
    float p  = 1.9875691500e-4f;
    p = fmaf(p, r, 1.3981999507e-3f);
    p = fmaf(p, r, 8.3334519073e-3f);
    p = fmaf(p, r, 4.1665795894e-2f);
    p = fmaf(p, r, 1.6666665459e-1f);
    p = fmaf(p, r, 5.0000000000e-1f);
    p = fmaf(p, r, 1.0f);
    p = fmaf(p, r, 1.0f);
    return p * __int_as_float(((int)kf + 127) << 23);
}

__device__ __forceinline__ void cp16(uint32_t dst_smem, const void* src) {
    asm volatile("cp.async.cg.shared.global [%0], [%1], 16;"
                 :: "r"(dst_smem), "l"(src));
}

// Thread-per-box decode: cp.async staging, per-thread argmax, 1024-bin
// score-bit histogram (bin = (bits - 0x3F000000) >> 13, clamped).
__global__ __launch_bounds__(DB) void decode_kernel(const float* __restrict__ y) {
    __shared__ float s[DB * ROW];
    __shared__ int   h[NBIN];
    const int b  = blockIdx.y;
    const int c0 = blockIdx.x * DB;
    const int nb = min(DB, NBOX - c0);
    const int nf4 = (nb * ROW) >> 2;
    const int t = threadIdx.x;

    #pragma unroll
    for (int j = 0; j < NBIN / DB; j++) h[t + j * DB] = 0;
    {
        const float4* src = (const float4*)(y + ((size_t)b * NBOX + c0) * ROW);
        uint32_t sbase;
        asm("{ .reg .u64 tmp; cvta.to.shared.u64 tmp, %1; cvt.u32.u64 %0, tmp; }"
            : "=r"(sbase) : "l"(s));
        for (int i = t; i < nf4; i += DB) cp16(sbase + i * 16, src + i);
        asm volatile("cp.async.commit_group;" ::: "memory");
        asm volatile("cp.async.wait_group 0;" ::: "memory");
    }
    __syncthreads();

    if (t < nb) {
        const float* row = s + t * ROW;
        // argmax over 81 classes; '>' keeps first occurrence (jnp.argmax)
        float best = row[0]; int bi = 0;
        #pragma unroll
        for (int c = 1; c < 81; c++) {
            float v = row[c];
            if (v > best) { best = v; bi = c; }
        }
        const int box = c0 + t;
        const int p = b * NBOX + box;
        if (bi != 0 && best >= 0.5f) {
            float o0 = row[81], o1 = row[82], o2 = row[83], o3 = row[84];
            float cxp = row[85], cyp = row[86], wp = row[87], hp = row[88];
            float va = row[89], vb = row[90], vc = row[91], vd = row[92];
            float cx = o0 * va * wp + cxp;
            float cy = o1 * vb * hp + cyp;
            float w  = exp_precise(o2 * vc) * wp;
            float hh = exp_precise(o3 * vd) * hp;
            float4 bx;
            bx.x = (cx - 0.5f * w)  * 512.0f;
            bx.y = (cy - 0.5f * hh) * 512.0f;
            bx.z = (cx + 0.5f * w)  * 512.0f;
            bx.w = (cy + 0.5f * hh) * 512.0f;
            unsigned sb = __float_as_uint(best);
            g_key[p] = ((u64)sb << 32) | (u64)(0xFFFFFFFFu - (unsigned)box);
            g_cls[p] = bi;
            g_box[p] = bx;
            int bin = min(NBIN - 1, (int)((sb - 0x3F000000u) >> 13));
            atomicAdd(&h[bin], 1);
        } else {
            g_key[p] = 0ull;
        }
    }
    __syncthreads();
    #pragma unroll
    for (int j = 0; j < NBIN / DB; j++) {
        int i = t + j * DB;
        int c = h[i];
        if (c) atomicAdd(&g_hist[b * NBIN + i], c);
    }
}

__device__ __forceinline__ bool iou_gt(const float4& a, const float4& q) {
    float iw = fminf(a.z, q.z) - fmaxf(a.x, q.x); iw = fmaxf(iw, 0.0f);
    float ih = fminf(a.w, q.w) - fmaxf(a.y, q.y); ih = fmaxf(ih, 0.0f);
    float inter  = iw * ih;
    float area_a = (a.z - a.x) * (a.w - a.y);
    float area_q = (q.z - q.x) * (q.w - q.y);
    return inter / (area_a + area_q - inter + 1e-12f) > 0.35f;
}

// One 1024-thread CTA per image. Floor from 1024-bin hist; compact keys >=
// floor into smem (3 serialized groups instead of 12); warp 0 greedy NMS;
// exact below-floor continuation if <10 picks (rare).
__global__ __launch_bounds__(PT) void post_kernel(float* __restrict__ out) {
    extern __shared__ __align__(16) char dsm[];
    float4* s_box = (float4*)dsm;                    // CCAP
    u64*    s_key = (u64*)(s_box + CCAP);            // CCAP
    __shared__ int s_h[NBIN];
    __shared__ int s_c[256];
    __shared__ int s_cnt;
    __shared__ u64 s_floor;

    const int b    = blockIdx.x;
    const int tid  = threadIdx.x;
    const int lane = tid & 31;
    const int base = b * NBOX;
    const unsigned FULL = 0xffffffffu;

    if (tid < NUM_PRED * 6) out[b * NUM_PRED * 6 + tid] = 0.0f;
    if (tid == 0) s_cnt = 0;
    if (tid < NBIN) {                                // read + zero hist
        s_h[tid] = g_hist[b * NBIN + tid];
        g_hist[b * NBIN + tid] = 0;
    }
    __syncthreads();
    if (tid < 256)
        s_c[tid] = s_h[tid*4] + s_h[tid*4+1] + s_h[tid*4+2] + s_h[tid*4+3];
    __syncthreads();

    // ---- floor finder (warp 0) ----
    if (tid < 32) {
        int W = 0;
        #pragma unroll
        for (int j = 0; j < 8; j++) W += s_c[lane * 8 + j];
        int suf = W;                                 // suffix sum over lanes
        #pragma unroll
        for (int o = 1; o < 32; o <<= 1) {
            int v = __shfl_down_sync(FULL, suf, o);
            if (lane + o < 32) suf += v;
        }
        int sufnext = __shfl_down_sync(FULL, suf, 1);
        if (lane == 31) sufnext = 0;
        unsigned mask = __ballot_sync(FULL, suf >= TARGET);
        if (mask == 0u) {
            if (lane == 0) s_floor = ((u64)0x3F000000u) << 32;   // admit all
        } else {
            int L = 31 - __clz(mask);
            if (lane == L) {
                int cum = sufnext;                   // < TARGET by construction
                int T = 32 * L;
                #pragma unroll
                for (int jb = 31; jb >= 0; jb--) {
                    cum += s_h[32 * L + jb];
                    if (cum >= TARGET) { T = 32 * L + jb; break; }
                }
                s_floor = ((u64)(0x3F000000u + ((unsigned)T << 13))) << 32;
            }
        }
    }
    __syncthreads();
    const u64 floork = s_floor;

    // ---- compact: 3 groups x 8 batched loads (1024 threads) ----
    for (int g = 0; g < 3; g++) {
        u64 k[8];
        #pragma unroll
        for (int j = 0; j < 8; j++) {
            int idx = tid + (g * 8 + j) * PT;
            k[j] = (idx < NBOX) ? g_key[base + idx] : 0ull;
        }
        #pragma unroll
        for (int j = 0; j < 8; j++) {
            bool pass = (k[j] >= floork);
            unsigned m = __ballot_sync(FULL, pass);
            if (m == 0u) continue;                   // common case
            if (pass) {
                int leader = __ffs(m) - 1;
                int wb;
                if (lane == leader) wb = atomicAdd(&s_cnt, __popc(m));
                wb = __shfl_sync(m, wb, leader);
                int slot = wb + __popc(m & ((1u << lane) - 1u));
                if (slot < CCAP) {
                    int idx = tid + (g * 8 + j) * PT;
                    s_key[slot] = k[j];
                    s_box[slot] = g_box[base + idx];
                }
            }
        }
    }
    __syncthreads();

    // ---- warp 0: greedy NMS over the score-prefix set ----
    if (tid >= 32) return;
    const bool fast = (s_cnt <= CCAP);
    const int M = fast ? s_cnt : 0;
    float4 pick = make_float4(0.f, 0.f, 0.f, 0.f);   // lane i holds pick i
    int np = 0;

    while (np < NUM_PRED) {
        u64 lb = 0; int ls = -1;
        for (int i = lane; i < M; i += 32) {
            u64 k = s_key[i];
            if (k > lb) { lb = k; ls = i; }
        }
        u64 gb = lb;
        #pragma unroll
        for (int o = 16; o > 0; o >>= 1) {
            u64 t2 = __shfl_xor_sync(FULL, gb, o);
            gb = t2 > gb ? t2 : gb;
        }
        if (gb == 0ull) break;
        unsigned own = __ballot_sync(FULL, lb == gb);
        int slot = __shfl_sync(FULL, ls, __ffs(own) - 1);
        float4 cand = s_box[slot];
        if (lane == (__ffs(own) - 1)) s_key[slot] = 0ull;
        __syncwarp();
        bool hit = (lane < np) && iou_gt(cand, pick);
        if (__ballot_sync(FULL, hit) == 0u) {
            if (lane == np) pick = cand;
            if (lane == 0) {
                unsigned orig = 0xFFFFFFFFu - (unsigned)gb;
                float* o = out + (b * NUM_PRED + np) * 6;
                o[0] = (float)g_cls[base + orig];
                o[1] = __uint_as_float((unsigned)(gb >> 32));
                o[2] = cand.x; o[3] = cand.y; o[4] = cand.z; o[5] = cand.w;
            }
            np++;
        }
    }

    // exact continuation below the floor (rare: <10 picks survived / overflow)
    u64 cont = fast ? floork : ~0ull;
    while (np < NUM_PRED) {
        u64 lb = 0;
        for (int i = lane; i < NBOX; i += 32) {
            u64 k = g_key[base + i];
            if (k < cont && k > lb) lb = k;
        }
        u64 gb = lb;
        #pragma unroll
        for (int o = 16; o > 0; o >>= 1) {
            u64 t2 = __shfl_xor_sync(FULL, gb, o);
            gb = t2 > gb ? t2 : gb;
        }
        if (gb == 0ull) break;
        cont = gb;
        unsigned orig = 0xFFFFFFFFu - (unsigned)gb;
        float4 cand = g_box[base + orig];
        bool hit = (lane < np) && iou_gt(cand, pick);
        if (__ballot_sync(FULL, hit) == 0u) {
            if (lane == np) pick = cand;
            if (lane == 0) {
                float* o = out + (b * NUM_PRED + np) * 6;
                o[0] = (float)g_cls[base + orig];
                o[1] = __uint_as_float((unsigned)(gb >> 32));
                o[2] = cand.x; o[3] = cand.y; o[4] = cand.z; o[5] = cand.w;
            }
            np++;
        }
    }
}

extern "C" void kernel_launch(void* const* d_in, const int* in_sizes, int n_in,
                              void* d_out, int out_size) {
    const float* y = (const float*)d_in[0];
    float* out = (float*)d_out;

    cudaFuncSetAttribute(post_kernel, cudaFuncAttributeMaxDynamicSharedMemorySize,
                         CCAP * 24);

    dim3 dgrid((NBOX + DB - 1) / DB, BATCH);
    decode_kernel<<<dgrid, DB>>>(y);

    post_kernel<<<BATCH, PT, CCAP * 24>>>(out);
}

// round 13
// speedup vs baseline: 1.8345x; 1.0380x over previous
#include <cuda_runtime.h>
#include <stdint.h>

#define BATCH 32
#define NBOX 24564
#define NBPAD 24576          // padded to 6144 uint4 per image
#define NB4 6144
#define ROW 93
#define NUM_PRED 10
#define DB 64                // boxes per decode CTA
#define NBIN 1024
#define CCAP 3072            // smem candidate capacity (24 B/entry = 72 KB)
#define TARGET 128
#define PT 1024              // post_kernel threads

typedef unsigned long long u64;

// Scratch (static device globals; zero-initialized at load).
// g_sb: score bits per box (0 = dead). Key is reconstructible:
//   key = ((u64)sb << 32) | (0xFFFFFFFF - idx). Padding [NBOX,NBPAD) stays 0.
__device__ unsigned g_sb [BATCH * NBPAD];
__device__ int      g_cls[BATCH * NBOX];
__device__ float4   g_box[BATCH * NBOX];
__device__ int      g_hist[BATCH * NBIN];

// Precise float exp: Cody-Waite + degree-6 FMA poly (~1 ulp), fast-math-proof.
__device__ __forceinline__ float exp_precise(float x) {
    x = fminf(fmaxf(x, -80.0f), 80.0f);
    float kf = rintf(x * 1.4426950408889634f);
    float r  = fmaf(-kf, 0.6931471824645996f, x);
    r        = fmaf(-kf, -1.904654323148236e-09f, r);
    float p  = 1.9875691500e-4f;
    p = fmaf(p, r, 1.3981999507e-3f);
    p = fmaf(p, r, 8.3334519073e-3f);
    p = fmaf(p, r, 4.1665795894e-2f);
    p = fmaf(p, r, 1.6666665459e-1f);
    p = fmaf(p, r, 5.0000000000e-1f);
    p = fmaf(p, r, 1.0f);
    p = fmaf(p, r, 1.0f);
    return p * __int_as_float(((int)kf + 127) << 23);
}

__device__ __forceinline__ void cp16(uint32_t dst_smem, const void* src) {
    asm volatile("cp.async.cg.shared.global [%0], [%1], 16;"
                 :: "r"(dst_smem), "l"(src));
}

// Thread-per-box decode: cp.async staging, per-thread argmax, 1024-bin
// score-bit histogram (bin = (bits - 0x3F000000) >> 13, clamped).
__global__ __launch_bounds__(DB) void decode_kernel(const float* __restrict__ y) {
    __shared__ float s[DB * ROW];
    __shared__ int   h[NBIN];
    const int b  = blockIdx.y;
    const int c0 = blockIdx.x * DB;
    const int nb = min(DB, NBOX - c0);
    const int nf4 = (nb * ROW) >> 2;
    const int t = threadIdx.x;

    #pragma unroll
    for (int j = 0; j < NBIN / DB; j++) h[t + j * DB] = 0;
    {
        const float4* src = (const float4*)(y + ((size_t)b * NBOX + c0) * ROW);
        uint32_t sbase;
        asm("{ .reg .u64 tmp; cvta.to.shared.u64 tmp, %1; cvt.u32.u64 %0, tmp; }"
            : "=r"(sbase) : "l"(s));
        for (int i = t; i < nf4; i += DB) cp16(sbase + i * 16, src + i);
        asm volatile("cp.async.commit_group;" ::: "memory");
        asm volatile("cp.async.wait_group 0;" ::: "memory");
    }
    __syncthreads();

    if (t < nb) {
        const float* row = s + t * ROW;
        // argmax over 81 classes; '>' keeps first occurrence (jnp.argmax)
        float best = row[0]; int bi = 0;
        #pragma unroll
        for (int c = 1; c < 81; c++) {
            float v = row[c];
            if (v > best) { best = v; bi = c; }
        }
        const int box = c0 + t;
        if (bi != 0 && best >= 0.5f) {
            float o0 = row[81], o1 = row[82], o2 = row[83], o3 = row[84];
            float cxp = row[85], cyp = row[86], wp = row[87], hp = row[88];
            float va = row[89], vb = row[90], vc = row[91], vd = row[92];
            float cx = o0 * va * wp + cxp;
            float cy = o1 * vb * hp + cyp;
            float w  = exp_precise(o2 * vc) * wp;
            float hh = exp_precise(o3 * vd) * hp;
            float4 bx;
            bx.x = (cx - 0.5f * w)  * 512.0f;
            bx.y = (cy - 0.5f * hh) * 512.0f;
            bx.z = (cx + 0.5f * w)  * 512.0f;
            bx.w = (cy + 0.5f * hh) * 512.0f;
            unsigned sb = __float_as_uint(best);
            g_sb[b * NBPAD + box] = sb;
            g_cls[b * NBOX + box] = bi;
            g_box[b * NBOX + box] = bx;
            int bin = min(NBIN - 1, (int)((sb - 0x3F000000u) >> 13));
            atomicAdd(&h[bin], 1);
        } else {
            g_sb[b * NBPAD + box] = 0u;
        }
    }
    __syncthreads();
    #pragma unroll
    for (int j = 0; j < NBIN / DB; j++) {
        int i = t + j * DB;
        int c = h[i];
        if (c) atomicAdd(&g_hist[b * NBIN + i], c);
    }
}

__device__ __forceinline__ bool iou_gt(const float4& a, const float4& q) {
    float iw = fminf(a.z, q.z) - fmaxf(a.x, q.x); iw = fmaxf(iw, 0.0f);
    float ih = fminf(a.w, q.w) - fmaxf(a.y, q.y); ih = fmaxf(ih, 0.0f);
    float inter  = iw * ih;
    float area_a = (a.z - a.x) * (a.w - a.y);
    float area_q = (q.z - q.x) * (q.w - q.y);
    return inter / (area_a + area_q - inter + 1e-12f) > 0.35f;
}

// One 1024-thread CTA per image. Floor from 1024-bin hist; uint4 scan of g_sb
// compacts passers (key reconstructed from sb+idx) into smem; warp 0 greedy
// NMS; exact below-floor continuation if <10 picks (rare).
__global__ __launch_bounds__(PT) void post_kernel(float* __restrict__ out) {
    extern __shared__ __align__(16) char dsm[];
    float4* s_box = (float4*)dsm;                    // CCAP
    u64*    s_key = (u64*)(s_box + CCAP);            // CCAP
    __shared__ int s_h[NBIN];
    __shared__ int s_c[256];
    __shared__ int s_cnt;
    __shared__ unsigned s_fsb;

    const int b    = blockIdx.x;
    const int tid  = threadIdx.x;
    const int lane = tid & 31;
    const int base = b * NBOX;
    const unsigned FULL = 0xffffffffu;

    if (tid < NUM_PRED * 6) out[b * NUM_PRED * 6 + tid] = 0.0f;
    if (tid == 0) s_cnt = 0;
    if (tid < NBIN) {                                // read + zero hist
        s_h[tid] = g_hist[b * NBIN + tid];
        g_hist[b * NBIN + tid] = 0;
    }
    __syncthreads();
    if (tid < 256)
        s_c[tid] = s_h[tid*4] + s_h[tid*4+1] + s_h[tid*4+2] + s_h[tid*4+3];
    __syncthreads();

    // ---- floor finder (warp 0) ----
    if (tid < 32) {
        int W = 0;
        #pragma unroll
        for (int j = 0; j < 8; j++) W += s_c[lane * 8 + j];
        int suf = W;                                 // suffix sum over lanes
        #pragma unroll
        for (int o = 1; o < 32; o <<= 1) {
            int v = __shfl_down_sync(FULL, suf, o);
            if (lane + o < 32) suf += v;
        }
        int sufnext = __shfl_down_sync(FULL, suf, 1);
        if (lane == 31) sufnext = 0;
        unsigned mask = __ballot_sync(FULL, suf >= TARGET);
        if (mask == 0u) {
            if (lane == 0) s_fsb = 0x3F000000u;      // admit all
        } else {
            int L = 31 - __clz(mask);
            if (lane == L) {
                int cum = sufnext;                   // < TARGET by construction
                int T = 32 * L;
                #pragma unroll
                for (int jb = 31; jb >= 0; jb--) {
                    cum += s_h[32 * L + jb];
                    if (cum >= TARGET) { T = 32 * L + jb; break; }
                }
                s_fsb = 0x3F000000u + ((unsigned)T << 13);
            }
        }
    }
    __syncthreads();
    const unsigned fsb = s_fsb;

    // ---- compact: 6 uint4 loads per thread (whole image, MLP-deep) ----
    {
        const uint4* sb4 = (const uint4*)(g_sb + b * NBPAD);
        uint4 v[6];
        #pragma unroll
        for (int g = 0; g < 6; g++) v[g] = sb4[tid + g * PT];
        #pragma unroll
        for (int g = 0; g < 6; g++) {
            unsigned a0 = v[g].x, a1 = v[g].y, a2 = v[g].z, a3 = v[g].w;
            bool any = (a0 >= fsb) | (a1 >= fsb) | (a2 >= fsb) | (a3 >= fsb);
            if (__ballot_sync(FULL, any) == 0u) continue;   // common case
            #pragma unroll
            for (int c = 0; c < 4; c++) {
                unsigned sb = (c == 0) ? a0 : (c == 1) ? a1 : (c == 2) ? a2 : a3;
                bool pass = (sb >= fsb);
                unsigned m = __ballot_sync(FULL, pass);
                if (m == 0u) continue;
                if (pass) {
                    int leader = __ffs(m) - 1;
                    int wb;
                    if (lane == leader) wb = atomicAdd(&s_cnt, __popc(m));
                    wb = __shfl_sync(m, wb, leader);
                    int slot = wb + __popc(m & ((1u << lane) - 1u));
                    if (slot < CCAP) {
                        int idx = (tid + g * PT) * 4 + c;
                        s_key[slot] = ((u64)sb << 32) |
                                      (u64)(0xFFFFFFFFu - (unsigned)idx);
                        s_box[slot] = g_box[base + idx];
                    }
                }
            }
        }
    }
    __syncthreads();

    // ---- warp 0: greedy NMS over the score-prefix set ----
    if (tid >= 32) return;
    const bool fast = (s_cnt <= CCAP);
    const int M = fast ? s_cnt : 0;
    float4 pick = make_float4(0.f, 0.f, 0.f, 0.f);   // lane i holds pick i
    int np = 0;

    while (np < NUM_PRED) {
        u64 lb = 0; int ls = -1;
        for (int i = lane; i < M; i += 32) {
            u64 k = s_key[i];
            if (k > lb) { lb = k; ls = i; }
        }
        u64 gb = lb;
        #pragma unroll
        for (int o = 16; o > 0; o >>= 1) {
            u64 t2 = __shfl_xor_sync(FULL, gb, o);
            gb = t2 > gb ? t2 : gb;
        }
        if (gb == 0ull) break;                       // prefix set exhausted
        unsigned own = __ballot_sync(FULL, lb == gb);
        int slot = __shfl_sync(FULL, ls, __ffs(own) - 1);
        float4 cand = s_box[slot];
        if (lane == (__ffs(own) - 1)) s_key[slot] = 0ull;
        __syncwarp();
        bool hit = (lane < np) && iou_gt(cand, pick);
        if (__ballot_sync(FULL, hit) == 0u) {
            if (lane == np) pick = cand;
            if (lane == 0) {
                unsigned orig = 0xFFFFFFFFu - (unsigned)gb;
                float* o = out + (b * NUM_PRED + np) * 6;
                o[0] = (float)g_cls[base + orig];
                o[1] = __uint_as_float((unsigned)(gb >> 32));
                o[2] = cand.x; o[3] = cand.y; o[4] = cand.z; o[5] = cand.w;
            }
            np++;
        }
    }

    // exact continuation below the floor (rare: <10 picks survived / overflow)
    u64 cont = fast ? (((u64)fsb) << 32) : ~0ull;
    while (np < NUM_PRED) {
        u64 lb = 0;
        for (int i = lane; i < NBOX; i += 32) {
            unsigned sb = g_sb[b * NBPAD + i];
            if (!sb) continue;
            u64 k = ((u64)sb << 32) | (u64)(0xFFFFFFFFu - (unsigned)i);
            if (k < cont && k > lb) lb = k;
        }
        u64 gb = lb;
        #pragma unroll
        for (int o = 16; o > 0; o >>= 1) {
            u64 t2 = __shfl_xor_sync(FULL, gb, o);
            gb = t2 > gb ? t2 : gb;
        }
        if (gb == 0ull) break;
        cont = gb;
        unsigned orig = 0xFFFFFFFFu - (unsigned)gb;
        float4 cand = g_box[base + orig];
        bool hit = (lane < np) && iou_gt(cand, pick);
        if (__ballot_sync(FULL, hit) == 0u) {
            if (lane == np) pick = cand;
            if (lane == 0) {
                float* o = out + (b * NUM_PRED + np) * 6;
                o[0] = (float)g_cls[base + orig];
                o[1] = __uint_as_float((unsigned)(gb >> 32));
                o[2] = cand.x; o[3] = cand.y; o[4] = cand.z; o[5] = cand.w;
            }
            np++;
        }
    }
}

extern "C" void kernel_launch(void* const* d_in, const int* in_sizes, int n_in,
                              void* d_out, int out_size) {
    const float* y = (const float*)d_in[0];
    float* out = (float*)d_out;

    cudaFuncSetAttribute(post_kernel, cudaFuncAttributeMaxDynamicSharedMemorySize,
                         CCAP * 24);

    dim3 dgrid((NBOX + DB - 1) / DB, BATCH);
    decode_kernel<<<dgrid, DB>>>(y);

    post_kernel<<<BATCH, PT, CCAP * 24>>>(out);
}